// round 1
// baseline (speedup 1.0000x reference)
#include <cuda_runtime.h>
#include <math.h>

#define D      128
#define TAU_INV 10.0f
#define NMAX   8192
#define TM     64
#define TN     256
#define JSPLIT 2

// scratch (device globals; no allocation allowed)
__device__ float g_pn[NMAX * D];
__device__ int   g_y2[NMAX];
__device__ float g_S[NMAX];
__device__ float g_P[NMAX];
__device__ float g_C[NMAX];

// ---------------------------------------------------------------------------
// Kernel 1: normalize rows of p = concat(z_i, z_j); zero accumulators; build y2
// grid = N blocks, 128 threads (one per D element)
// ---------------------------------------------------------------------------
__global__ void prep_kernel(const float* __restrict__ zi,
                            const float* __restrict__ zj,
                            const int*   __restrict__ y, int B) {
    int row = blockIdx.x;
    int t   = threadIdx.x;  // 0..127
    const float* src = (row < B) ? (zi + (size_t)row * D)
                                 : (zj + (size_t)(row - B) * D);
    float v  = src[t];
    float ss = v * v;
    #pragma unroll
    for (int o = 16; o > 0; o >>= 1) ss += __shfl_xor_sync(0xffffffffu, ss, o);
    __shared__ float ws[4];
    int warp = t >> 5, lane = t & 31;
    if (lane == 0) ws[warp] = ss;
    __syncthreads();
    float tot  = ws[0] + ws[1] + ws[2] + ws[3];
    float norm = fmaxf(sqrtf(tot), 1e-8f);
    g_pn[(size_t)row * D + t] = v / norm;
    if (t == 0) {
        g_y2[row] = y[(row < B) ? row : (row - B)];
        g_S[row] = 0.f; g_P[row] = 0.f; g_C[row] = 0.f;
    }
}

// ---------------------------------------------------------------------------
// Kernel 2: main. Each block owns TM=64 rows and one of JSPLIT=2 j-stripes.
// GEMM tile: 64 (rows) x 256 (cols j) per iteration, full K=128 in smem.
// 256 threads, 8x8 micro-tile per thread. Fused epilogue accumulates
// exp-sum / pos-sum / pos-count per row; atomics merge the two j-splits.
// ---------------------------------------------------------------------------
__global__ __launch_bounds__(256)
void main_kernel(int N) {
    extern __shared__ float sm[];
    float* A_s = sm;                 // [k][64]  : 128*64  floats = 32 KB
    float* B_s = sm + D * TM;        // [k][256] : 128*256 floats = 128 KB
    __shared__ int ys[TN];
    __shared__ int yr[TM];

    int tid = threadIdx.x;
    int ty  = tid >> 5;   // warp id 0..7 -> owns rows ty*8..ty*8+7
    int tx  = tid & 31;   // lane

    int rowTile = blockIdx.x >> 1;
    int split   = blockIdx.x & 1;
    int rowBase = rowTile * TM;

    // Load A tile (64 rows x 128 k) transposed into A_s[k][r]
    {
        int r     = tid & 63;
        int kbase = (tid >> 6) * 32;   // 0/32/64/96
        const float4* src = (const float4*)(g_pn + (size_t)(rowBase + r) * D + kbase);
        #pragma unroll
        for (int k4 = 0; k4 < 8; k4++) {
            float4 v = src[k4];
            int k = kbase + k4 * 4;
            A_s[(k + 0) * TM + r] = v.x;
            A_s[(k + 1) * TM + r] = v.y;
            A_s[(k + 2) * TM + r] = v.z;
            A_s[(k + 3) * TM + r] = v.w;
        }
        if (tid < TM) yr[tid] = g_y2[rowBase + tid];
    }
    __syncthreads();

    int myrowy[8];
    #pragma unroll
    for (int rr = 0; rr < 8; rr++) myrowy[rr] = yr[ty * 8 + rr];

    float expsum[8], possum[8], poscnt[8];
    #pragma unroll
    for (int i = 0; i < 8; i++) { expsum[i] = 0.f; possum[i] = 0.f; poscnt[i] = 0.f; }

    int jTiles = N / TN;  // 32
    for (int jt = split; jt < jTiles; jt += JSPLIT) {
        int jbase = jt * TN;
        __syncthreads();   // protect B_s from previous iteration's readers
        // Load B tile: thread tid loads full row (jbase+tid), writes transposed
        {
            const float4* src = (const float4*)(g_pn + (size_t)(jbase + tid) * D);
            #pragma unroll
            for (int k4 = 0; k4 < 32; k4++) {
                float4 v = src[k4];
                int k = k4 * 4;
                B_s[(k + 0) * TN + tid] = v.x;
                B_s[(k + 1) * TN + tid] = v.y;
                B_s[(k + 2) * TN + tid] = v.z;
                B_s[(k + 3) * TN + tid] = v.w;
            }
            ys[tid] = g_y2[jbase + tid];
        }
        __syncthreads();

        float acc[8][8];
        #pragma unroll
        for (int a = 0; a < 8; a++)
            #pragma unroll
            for (int b = 0; b < 8; b++) acc[a][b] = 0.f;

        // cols per thread: group0 = tx*4..tx*4+3, group1 = 128+tx*4..+3 (conflict-free LDS.128)
        #pragma unroll 4
        for (int k = 0; k < D; k++) {
            float4 a0 = *(const float4*)&A_s[k * TM + ty * 8];       // broadcast within warp
            float4 a1 = *(const float4*)&A_s[k * TM + ty * 8 + 4];
            float4 b0 = *(const float4*)&B_s[k * TN + tx * 4];
            float4 b1 = *(const float4*)&B_s[k * TN + 128 + tx * 4];
            float av[8] = {a0.x, a0.y, a0.z, a0.w, a1.x, a1.y, a1.z, a1.w};
            float bv[8] = {b0.x, b0.y, b0.z, b0.w, b1.x, b1.y, b1.z, b1.w};
            #pragma unroll
            for (int rr = 0; rr < 8; rr++)
                #pragma unroll
                for (int cc = 0; cc < 8; cc++)
                    acc[rr][cc] = fmaf(av[rr], bv[cc], acc[rr][cc]);
        }

        // fused epilogue: sim = dot * (1/tau); mask diagonal; pos accumulation
        #pragma unroll
        for (int cc = 0; cc < 8; cc++) {
            int clocal = (cc < 4) ? (tx * 4 + cc) : (128 + tx * 4 + (cc - 4));
            int j  = jbase + clocal;
            int yj = ys[clocal];
            #pragma unroll
            for (int rr = 0; rr < 8; rr++) {
                int   i   = rowBase + ty * 8 + rr;
                float sim = acc[rr][cc] * TAU_INV;
                if (j != i) {
                    expsum[rr] += __expf(sim);
                    if (yj == myrowy[rr]) { possum[rr] += sim; poscnt[rr] += 1.f; }
                }
            }
        }
    }

    // reduce across the 32 lanes of each warp (all lanes share the warp's 8 rows)
    #pragma unroll
    for (int rr = 0; rr < 8; rr++) {
        float e = expsum[rr], p = possum[rr], c = poscnt[rr];
        #pragma unroll
        for (int o = 16; o > 0; o >>= 1) {
            e += __shfl_xor_sync(0xffffffffu, e, o);
            p += __shfl_xor_sync(0xffffffffu, p, o);
            c += __shfl_xor_sync(0xffffffffu, c, o);
        }
        if (tx == 0) {
            int i = rowBase + ty * 8 + rr;
            atomicAdd(&g_S[i], e);
            atomicAdd(&g_P[i], p);
            atomicAdd(&g_C[i], c);
        }
    }
}

// ---------------------------------------------------------------------------
// Kernel 3: loss = -sum_i (P_i/C_i - log S_i)
// ---------------------------------------------------------------------------
__global__ void finalize_kernel(float* __restrict__ out, int N) {
    int t = threadIdx.x;  // 256
    float local = 0.f;
    for (int i = t; i < N; i += 256)
        local -= g_P[i] / g_C[i] - logf(g_S[i]);
    #pragma unroll
    for (int o = 16; o > 0; o >>= 1) local += __shfl_xor_sync(0xffffffffu, local, o);
    __shared__ float ws[8];
    if ((t & 31) == 0) ws[t >> 5] = local;
    __syncthreads();
    if (t < 8) {
        float v = ws[t];
        #pragma unroll
        for (int o = 4; o > 0; o >>= 1) v += __shfl_xor_sync(0x000000ffu, v, o);
        if (t == 0) out[0] = v;
    }
}

// ---------------------------------------------------------------------------
extern "C" void kernel_launch(void* const* d_in, const int* in_sizes, int n_in,
                              void* d_out, int out_size) {
    const float* zi = (const float*)d_in[0];
    const float* zj = (const float*)d_in[1];
    const int*   y  = (const int*)d_in[2];
    int B = in_sizes[2];
    int N = 2 * B;

    prep_kernel<<<N, 128>>>(zi, zj, y, B);

    int smem = (D * TM + D * TN) * (int)sizeof(float);  // 160 KB
    cudaFuncSetAttribute(main_kernel, cudaFuncAttributeMaxDynamicSharedMemorySize, smem);
    main_kernel<<<(N / TM) * JSPLIT, 256, smem>>>(N);

    finalize_kernel<<<1, 256>>>((float*)d_out, N);
}

// round 4
// speedup vs baseline: 6.0181x; 6.0181x over previous
#include <cuda_runtime.h>
#include <cuda_fp16.h>
#include <cstdint>
#include <math.h>

#define D       128
#define NMAX    8192
#define TAU_INV 10.0f
#define TM      128
#define TN      128
#define JSPLIT  2

// scratch (device globals; no allocation allowed)
__device__ __half g_ph[NMAX * D];
__device__ int    g_y2[NMAX];
__device__ float  g_S[NMAX];
__device__ float  g_P[NMAX];
__device__ float  g_C[NMAX];

// ---------------------------------------------------------------------------
// helpers (baseline PTX only: sm_80-era features, legal on target sm_103)
// ---------------------------------------------------------------------------
__device__ __forceinline__ uint32_t smem_u32(const void* p) {
    uint32_t a;
    asm("{ .reg .u64 t; cvta.to.shared.u64 t, %1; cvt.u32.u64 %0, t; }"
        : "=r"(a) : "l"(p));
    return a;
}
__device__ __forceinline__ void ldsm4(uint32_t r[4], uint32_t addr) {
    asm volatile("ldmatrix.sync.aligned.m8n8.x4.shared.b16 {%0,%1,%2,%3}, [%4];"
                 : "=r"(r[0]), "=r"(r[1]), "=r"(r[2]), "=r"(r[3]) : "r"(addr));
}
__device__ __forceinline__ void mma16816(float c[4], const uint32_t a[4],
                                         const uint32_t b[2]) {
    asm volatile(
        "mma.sync.aligned.m16n8k16.row.col.f32.f16.f16.f32 "
        "{%0,%1,%2,%3}, {%4,%5,%6,%7}, {%8,%9}, {%0,%1,%2,%3};"
        : "+f"(c[0]), "+f"(c[1]), "+f"(c[2]), "+f"(c[3])
        : "r"(a[0]), "r"(a[1]), "r"(a[2]), "r"(a[3]), "r"(b[0]), "r"(b[1]));
}
__device__ __forceinline__ void cp16(uint32_t saddr, const void* g) {
    asm volatile("cp.async.cg.shared.global [%0], [%1], 16;"
                 :: "r"(saddr), "l"(g) : "memory");
}
#define CP_COMMIT() asm volatile("cp.async.commit_group;" ::: "memory")

// smem layout (byte offsets in dynamic smem)
#define A_OFF  0u
#define B_OFF  32768u          // two 32 KB B buffers
#define Y_OFF  98304u          // two 512 B label buffers
#define SMEM_TOTAL (98304 + 1024)

// ---------------------------------------------------------------------------
// Kernel 1: normalize rows of p = concat(z_i,z_j) -> f16 table, labels, zeros
// ---------------------------------------------------------------------------
__global__ void prep_kernel(const float* __restrict__ zi,
                            const float* __restrict__ zj,
                            const int*   __restrict__ y, int B) {
    int warp = threadIdx.x >> 5, lane = threadIdx.x & 31;
    int row  = blockIdx.x * 8 + warp;
    const float* src = (row < B) ? (zi + (size_t)row * D)
                                 : (zj + (size_t)(row - B) * D);
    float4 v = ((const float4*)src)[lane];
    float ss = v.x * v.x + v.y * v.y + v.z * v.z + v.w * v.w;
    #pragma unroll
    for (int o = 16; o > 0; o >>= 1) ss += __shfl_xor_sync(0xffffffffu, ss, o);
    float s = 1.f / fmaxf(sqrtf(ss), 1e-8f);
    __half2 h0 = __floats2half2_rn(v.x * s, v.y * s);
    __half2 h1 = __floats2half2_rn(v.z * s, v.w * s);
    uint2 u;
    u.x = *reinterpret_cast<unsigned int*>(&h0);
    u.y = *reinterpret_cast<unsigned int*>(&h1);
    ((uint2*)(g_ph + (size_t)row * D))[lane] = u;
    if (lane == 0) {
        g_y2[row] = y[(row < B) ? row : (row - B)];
        g_S[row] = 0.f; g_P[row] = 0.f; g_C[row] = 0.f;
    }
}

// ---------------------------------------------------------------------------
// Kernel 2: HMMA (mma.sync) GEMM with fused contrastive epilogue.
// 256 threads = 8 warps (2 m x 4 n). Per warp: 64x32 tile = 4x4 m16n8k16 frags.
// B tiles double-buffered via cp.async. Accumulators live in registers.
// ---------------------------------------------------------------------------
__global__ __launch_bounds__(256, 1)
void main_kernel() {
    extern __shared__ char sm[];
    const uint32_t smb = smem_u32(sm);

    const int tid = threadIdx.x, lane = tid & 31, wid = tid >> 5;
    const int warp_m = wid >> 2, warp_n = wid & 3;
    const int rowTile = blockIdx.x >> 1, split = blockIdx.x & 1;
    const int rowBase = rowTile * TM;
    const int NT = NMAX / TN / JSPLIT;  // 32 j-tiles per CTA

    // ---- load A tile (128 rows x 128 f16) with xor-16B-chunk swizzle -------
    for (int u = tid; u < TM * 16; u += 256) {
        int r = u >> 4, c = u & 15;
        uint4 v = ((const uint4*)(g_ph + (size_t)(rowBase + r) * D))[c];
        *(uint4*)(sm + A_OFF + (uint32_t)r * 256u + (uint32_t)((c ^ (r & 7)) << 4)) = v;
    }

    // ---- prefetch B tile 0 --------------------------------------------------
    {
        int jbase = split * TN;
        for (int u = tid; u < TN * 16; u += 256) {
            int r = u >> 4, c = u & 15;
            cp16(smb + B_OFF + (uint32_t)r * 256u + (uint32_t)((c ^ (r & 7)) << 4),
                 g_ph + (size_t)(jbase + r) * D + c * 8);
        }
        if (tid < 32) cp16(smb + Y_OFF + tid * 16u, g_y2 + jbase + tid * 4);
        CP_COMMIT();
    }

    // ---- per-thread ldmatrix address precompute -----------------------------
    const int g = lane >> 3;
    // A: lanes 0-7 m0(rows+0,k+0) 8-15 m1(rows+8,k+0) 16-23 m2(rows+0,k+8) 24-31 m3(rows+8,k+8)
    uint32_t a_off[4], a_msk[4];
    #pragma unroll
    for (int mt = 0; mt < 4; mt++) {
        int row = warp_m * 64 + mt * 16 + (g & 1) * 8 + (lane & 7);
        a_off[mt] = smb + A_OFF + (uint32_t)row * 256u;
        a_msk[mt] = (uint32_t)(row & 7);
    }
    const int a_cadd = g >> 1;
    // B: lanes 0-7 n+0,k+0  8-15 n+0,k+8  16-23 n+8,k+0  24-31 n+8,k+8
    uint32_t b_row[2], b_msk[2];
    #pragma unroll
    for (int nt2 = 0; nt2 < 2; nt2++) {
        int row = warp_n * 32 + nt2 * 16 + (g >> 1) * 8 + (lane & 7);
        b_row[nt2] = (uint32_t)row * 256u;
        b_msk[nt2] = (uint32_t)(row & 7);
    }
    const int b_cadd = g & 1;

    // ---- per-row labels for this thread's 8 row-slots -----------------------
    // slot s: mt = s>>1, half = s&1 -> row = rowBase + warp_m*64 + mt*16 + (lane>>2) + half*8
    int   yi[8];
    float es[8], ps[8], cn[8];
    #pragma unroll
    for (int s = 0; s < 8; s++) {
        int row = rowBase + warp_m * 64 + (s >> 1) * 16 + (lane >> 2) + (s & 1) * 8;
        yi[s] = g_y2[row];
        es[s] = 0.f; ps[s] = 0.f; cn[s] = 0.f;
    }
    const int irow0 = rowBase + warp_m * 64 + (lane >> 2);

    // ---- main j loop ---------------------------------------------------------
    for (int t = 0; t < NT; t++) {
        __syncthreads();   // everyone done reading the buffer we'll overwrite
        if (t + 1 < NT) {
            int jb = ((t + 1) * JSPLIT + split) * TN;
            uint32_t boff = B_OFF + ((t + 1) & 1) * 32768u;
            for (int u = tid; u < TN * 16; u += 256) {
                int r = u >> 4, c = u & 15;
                cp16(smb + boff + (uint32_t)r * 256u + (uint32_t)((c ^ (r & 7)) << 4),
                     g_ph + (size_t)(jb + r) * D + c * 8);
            }
            if (tid < 32)
                cp16(smb + Y_OFF + ((t + 1) & 1) * 512u + tid * 16u, g_y2 + jb + tid * 4);
            CP_COMMIT();
            asm volatile("cp.async.wait_group 1;" ::: "memory");
        } else {
            asm volatile("cp.async.wait_group 0;" ::: "memory");
        }
        __syncthreads();   // cp.async data visible to all threads

        const int buf   = t & 1;
        const int jbase = (t * JSPLIT + split) * TN;
        const uint32_t bbase = smb + B_OFF + (uint32_t)buf * 32768u;
        const int* ys = (const int*)(sm + Y_OFF + buf * 512u);

        float acc[4][4][4];
        #pragma unroll
        for (int mt = 0; mt < 4; mt++)
            #pragma unroll
            for (int nt = 0; nt < 4; nt++)
                #pragma unroll
                for (int k = 0; k < 4; k++) acc[mt][nt][k] = 0.f;

        #pragma unroll
        for (int ks = 0; ks < 8; ks++) {
            uint32_t af[4][4], bf[2][4];
            #pragma unroll
            for (int mt = 0; mt < 4; mt++)
                ldsm4(af[mt], a_off[mt] +
                      (uint32_t)(((2 * ks + a_cadd) ^ a_msk[mt]) << 4));
            #pragma unroll
            for (int nt2 = 0; nt2 < 2; nt2++)
                ldsm4(bf[nt2], bbase + b_row[nt2] +
                      (uint32_t)(((2 * ks + b_cadd) ^ b_msk[nt2]) << 4));
            #pragma unroll
            for (int mt = 0; mt < 4; mt++)
                #pragma unroll
                for (int nt = 0; nt < 4; nt++)
                    mma16816(acc[mt][nt], af[mt], &bf[nt >> 1][(nt & 1) * 2]);
        }

        // ---- fused epilogue on register fragments ----------------------------
        #pragma unroll
        for (int nt = 0; nt < 4; nt++) {
            int col = warp_n * 32 + nt * 8 + (lane & 3) * 2;
            int j0 = jbase + col;
            int yj0 = ys[col], yj1 = ys[col + 1];
            #pragma unroll
            for (int mt = 0; mt < 4; mt++) {
                int iA = irow0 + mt * 16;       // rows for c0/c1
                int iB = iA + 8;                // rows for c2/c3
                int sA = mt * 2, sB = mt * 2 + 1;
                #pragma unroll
                for (int q = 0; q < 4; q++) {
                    float c   = acc[mt][nt][q];
                    int   jj  = j0 + (q & 1);
                    int   ii  = (q < 2) ? iA : iB;
                    int   ss  = (q < 2) ? sA : sB;
                    int   yjj = (q & 1) ? yj1 : yj0;
                    float sim = c * TAU_INV;
                    float e   = __expf(sim);
                    bool  diag = (jj == ii);
                    bool  pos  = (yjj == yi[ss]) && !diag;
                    es[ss] += diag ? 0.f : e;
                    ps[ss] += pos ? sim : 0.f;
                    cn[ss] += pos ? 1.f : 0.f;
                }
            }
        }
    }

    // ---- reduce across the 4 lanes sharing each row, then atomics ----------
    #pragma unroll
    for (int s = 0; s < 8; s++) {
        float e = es[s], p = ps[s], c = cn[s];
        e += __shfl_xor_sync(0xffffffffu, e, 1);
        e += __shfl_xor_sync(0xffffffffu, e, 2);
        p += __shfl_xor_sync(0xffffffffu, p, 1);
        p += __shfl_xor_sync(0xffffffffu, p, 2);
        c += __shfl_xor_sync(0xffffffffu, c, 1);
        c += __shfl_xor_sync(0xffffffffu, c, 2);
        if ((lane & 3) == 0) {
            int row = rowBase + warp_m * 64 + (s >> 1) * 16 + (lane >> 2) + (s & 1) * 8;
            atomicAdd(&g_S[row], e);
            atomicAdd(&g_P[row], p);
            atomicAdd(&g_C[row], c);
        }
    }
}

// ---------------------------------------------------------------------------
// Kernel 3: loss = -sum_i (P_i/C_i - log S_i)
// ---------------------------------------------------------------------------
__global__ void finalize_kernel(float* __restrict__ out, int N) {
    int t = threadIdx.x;  // 256
    float local = 0.f;
    for (int i = t; i < N; i += 256)
        local -= g_P[i] / g_C[i] - logf(g_S[i]);
    #pragma unroll
    for (int o = 16; o > 0; o >>= 1) local += __shfl_xor_sync(0xffffffffu, local, o);
    __shared__ float ws[8];
    if ((t & 31) == 0) ws[t >> 5] = local;
    __syncthreads();
    if (t < 8) {
        float v = ws[t];
        #pragma unroll
        for (int o = 4; o > 0; o >>= 1) v += __shfl_xor_sync(0x000000ffu, v, o);
        if (t == 0) out[0] = v;
    }
}

// ---------------------------------------------------------------------------
extern "C" void kernel_launch(void* const* d_in, const int* in_sizes, int n_in,
                              void* d_out, int out_size) {
    const float* zi = (const float*)d_in[0];
    const float* zj = (const float*)d_in[1];
    const int*   y  = (const int*)d_in[2];
    int B = in_sizes[2];
    int N = 2 * B;

    prep_kernel<<<N / 8, 256>>>(zi, zj, y, B);

    cudaFuncSetAttribute(main_kernel, cudaFuncAttributeMaxDynamicSharedMemorySize,
                         SMEM_TOTAL);
    main_kernel<<<(N / TM) * JSPLIT, 256, SMEM_TOTAL>>>();

    finalize_kernel<<<1, 256>>>((float*)d_out, N);
}